// round 9
// baseline (speedup 1.0000x reference)
#include <cuda_runtime.h>
#include <cstring>

// B-spline layer via per-span cubic collapse:
//   u = 61*x, m = floor(u), t = u-m
//   out[b,f] = A0(m,f) + A1 t + A2 t^2 + A3 t^3
// A_c(m,f) = sum_r basis[m][r][c] * cp[m+r][f], bias folded into A0.
// Basis polys are input-independent -> built on host, passed by value
// (constant bank). R9: the A-table is built ONCE by a tiny producer kernel
// into a __device__ global (125 KB, L2-resident); eval CTAs just bulk-copy
// their 62.5 KB feature-half into smem (coalesced LDG.128->STS.128) and
// evaluate. Kills the 256x redundant per-CTA fold of R8.

#define NF    128
#define FH    64            // features per eval CTA
#define NSPAN 61
#define TB    512
#define RPB   128           // rows per eval block
#define RPT   16            // rows per thread
#define UC    4             // rows per eval chunk

#define TAB_ENTRIES (NSPAN * NF)         // 7808
#define SMEM_BYTES  (NSPAN * FH * 16)    // 62.5 KB

struct BasisTab {
    float4 b[NSPAN * 4];    // [m][r] -> (c0,c1,c2,c3) coeffs in t
};

__device__ float4 g_table[TAB_ENTRIES];  // 125 KB staging (L2-hot)

// ---- producer: fold cp + bias with basis polys -> g_table, once ----
__global__ void __launch_bounds__(TB)
build_table_kernel(const BasisTab bt,
                   const float* __restrict__ cp,
                   const float* __restrict__ bias)
{
    const int idx = blockIdx.x * TB + threadIdx.x;
    if (idx >= TAB_ENTRIES) return;
    const int m = idx >> 7;          // warp-uniform -> bt reads are LDC
    const int f = idx & (NF - 1);
    const float c0 = cp[(m + 0) * NF + f];
    const float c1 = cp[(m + 1) * NF + f];
    const float c2 = cp[(m + 2) * NF + f];
    const float c3 = cp[(m + 3) * NF + f];
    const float4 b0 = bt.b[m * 4 + 0];
    const float4 b1 = bt.b[m * 4 + 1];
    const float4 b2 = bt.b[m * 4 + 2];
    const float4 b3 = bt.b[m * 4 + 3];
    float4 A;
    A.x = fmaf(c0, b0.x, fmaf(c1, b1.x, fmaf(c2, b2.x, fmaf(c3, b3.x, bias[f]))));
    A.y = fmaf(c0, b0.y, fmaf(c1, b1.y, fmaf(c2, b2.y, c3 * b3.y)));
    A.z = fmaf(c0, b0.z, fmaf(c1, b1.z, fmaf(c2, b2.z, c3 * b3.z)));
    A.w = fmaf(c0, b0.w, fmaf(c1, b1.w, fmaf(c2, b2.w, c3 * b3.w)));
    g_table[idx] = A;
}

// ---- consumer: copy half-table to smem, evaluate ----
template <bool GUARD>
__global__ void __launch_bounds__(TB, 2)
bspline_eval_kernel(const float* __restrict__ x,
                    float* __restrict__ out,
                    int B)
{
    extern __shared__ float4 table[];   // [61*64] this CTA's feature half

    const int tid   = threadIdx.x;
    const int fhalf = blockIdx.x & 1;
    const int tile  = blockIdx.x >> 1;
    const int fl    = tid & (FH - 1);
    const int lrow  = tid >> 6;                 // 0..7
    const int fg    = fhalf * FH + fl;

    const int rowBase = tile * RPB + lrow;

    // stage A: front-load all x (MLP = 16); copy phase hides DRAM latency
    float xv[RPT];
#pragma unroll
    for (int j = 0; j < RPT; j++) {
        const int row = rowBase + j * 8;
        if (!GUARD || row < B) xv[j] = x[row * NF + fg];
    }

    // stage B: bulk copy of this half of the table (coalesced, L2-hit)
    const float4* __restrict__ src = g_table + fhalf * FH;
#pragma unroll
    for (int it = 0; it < (NSPAN * FH + TB - 1) / TB; it++) {
        const int idx = tid + it * TB;
        if (idx < NSPAN * FH) {
            const int m  = idx >> 6;
            const int ff = idx & (FH - 1);
            table[idx] = src[m * NF + ff];
        }
    }
    __syncthreads();

    // stage C: eval (LDS.128 conflict-free + 3-FMA Horner)
#pragma unroll
    for (int chunk = 0; chunk < RPT / UC; chunk++) {
        float  t[UC];
        float4 A[UC];
#pragma unroll
        for (int jj = 0; jj < UC; jj++) {
            const int j = chunk * UC + jj;
            const float u  = xv[j] * 61.0f;
            const float fm = floorf(u);          // x in [0,1) -> m in [0,60]
            t[jj] = u - fm;
            A[jj] = table[(int)fm * FH + fl];
        }
#pragma unroll
        for (int jj = 0; jj < UC; jj++) {
            const int j = chunk * UC + jj;
            float r = fmaf(A[jj].w, t[jj], A[jj].z);
            r = fmaf(r, t[jj], A[jj].y);
            r = fmaf(r, t[jj], A[jj].x);
            const int row = rowBase + j * 8;
            if (!GUARD || row < B) out[row * NF + fg] = r;
        }
    }
}

// ---- host-side basis polynomial construction (input-independent) ----
static inline double knotd(int im3) {
    double v = (double)im3;
    if (v < 0.0) v = 0.0;
    if (v > 61.0) v = 61.0;
    return v;
}

static void build_basis(BasisTab* bt)
{
    for (int m = 0; m < NSPAN; m++) {
        double P[4][4];
        memset(P, 0, sizeof(P));
        P[0][0] = 1.0;   // k=0: N_{m+3}^0 = 1 on the span

        for (int k = 1; k <= 3; k++) {
            double Q[4][4];
            memset(Q, 0, sizeof(Q));
            for (int j = 0; j <= k; j++) {
                const int i = m + 3 - k + j;
                const double ti   = knotd(i - 3);
                const double ti1  = knotd(i - 2);
                const double tik  = knotd(i - 3 + k);
                const double tik1 = knotd(i - 2 + k);
                if (j >= 1 && tik != ti) {
                    const double inv = 1.0 / (tik - ti);
                    const double a0  = ((double)m - ti) * inv;
                    for (int c = 0; c < 4; c++) Q[j][c]     += a0  * P[j - 1][c];
                    for (int c = 0; c < 3; c++) Q[j][c + 1] += inv * P[j - 1][c];
                }
                if (j <= k - 1 && tik1 != ti1) {
                    const double inv = 1.0 / (tik1 - ti1);
                    const double b0  = (tik1 - (double)m) * inv;
                    for (int c = 0; c < 4; c++) Q[j][c]     += b0  * P[j][c];
                    for (int c = 0; c < 3; c++) Q[j][c + 1] -= inv * P[j][c];
                }
            }
            memcpy(P, Q, sizeof(P));
        }
        for (int r = 0; r < 4; r++) {
            bt->b[m * 4 + r].x = (float)P[r][0];
            bt->b[m * 4 + r].y = (float)P[r][1];
            bt->b[m * 4 + r].z = (float)P[r][2];
            bt->b[m * 4 + r].w = (float)P[r][3];
        }
    }
}

extern "C" void kernel_launch(void* const* d_in, const int* in_sizes, int n_in,
                              void* d_out, int out_size)
{
    const float* x    = (const float*)d_in[0];
    const float* cp   = (const float*)d_in[1];
    const float* bias = (const float*)d_in[2];
    float* out = (float*)d_out;

    const int B = in_sizes[0] / NF;   // 16384 rows

    static BasisTab bt;
    build_basis(&bt);                 // deterministic per call

    static bool attrSet = false;
    if (!attrSet) {
        cudaFuncSetAttribute(bspline_eval_kernel<false>,
                             cudaFuncAttributeMaxDynamicSharedMemorySize, SMEM_BYTES);
        cudaFuncSetAttribute(bspline_eval_kernel<true>,
                             cudaFuncAttributeMaxDynamicSharedMemorySize, SMEM_BYTES);
        attrSet = true;
    }

    // producer: build the 61x128 coefficient table once
    build_table_kernel<<<(TAB_ENTRIES + TB - 1) / TB, TB>>>(bt, cp, bias);

    // consumer: evaluate
    if ((B % RPB) == 0) {
        const int grid = (B / RPB) * 2;                 // 256 CTAs
        bspline_eval_kernel<false><<<grid, TB, SMEM_BYTES>>>(x, out, B);
    } else {
        const int grid = ((B + RPB - 1) / RPB) * 2;
        bspline_eval_kernel<true><<<grid, TB, SMEM_BYTES>>>(x, out, B);
    }
}

// round 10
// speedup vs baseline: 1.2610x; 1.2610x over previous
#include <cuda_runtime.h>
#include <cstring>

// B-spline layer via per-span cubic collapse:
//   u = 61*x, m = floor(u), t = u-m
//   out[b,f] = A0(m,f) + A1 t + A2 t^2 + A3 t^3
// A_c(m,f) = sum_r basis[m][r][c] * cp[m+r][f], bias folded into A0.
// Basis polys: host-built (double precision), passed by value (constant bank).
// R10: occupancy experiment. Producer builds the 61x128 float4 table once
// (L2-resident). Eval CTAs own a 32-feature QUARTER: smem table 31.25 KB ->
// 5 CTAs/SM (40 warps/SM), 256 threads, ~40 regs, software-pipelined x loads.

#define NF    128
#define FQ    32            // features per eval CTA (quarter)
#define NSPAN 61
#define TBP   256           // producer block
#define TBE   256           // eval block
#define RPB   128           // rows per eval CTA
#define UC    4             // rows per chunk
#define NCH   4             // chunks (RPB / (8 warps * UC) ... 8 warps * 16 rows)

#define TAB_ENTRIES (NSPAN * NF)            // 7808
#define QT_ENTRIES  (NSPAN * FQ)            // 1952
#define SMEM_BYTES  (QT_ENTRIES * 16)       // 31.25 KB

struct BasisTab {
    float4 b[NSPAN * 4];    // [m][r] -> (c0,c1,c2,c3) coeffs in t
};

__device__ float4 g_table[TAB_ENTRIES];     // 125 KB staging (L2-hot)

// ---- producer: fold cp + bias with basis polys -> g_table, once ----
__global__ void __launch_bounds__(TBP)
build_table_kernel(const BasisTab bt,
                   const float* __restrict__ cp,
                   const float* __restrict__ bias)
{
    const int idx = blockIdx.x * TBP + threadIdx.x;
    if (idx >= TAB_ENTRIES) return;
    const int m = idx >> 7;                 // warp-uniform -> bt reads are LDC
    const int f = idx & (NF - 1);
    const float c0 = cp[(m + 0) * NF + f];
    const float c1 = cp[(m + 1) * NF + f];
    const float c2 = cp[(m + 2) * NF + f];
    const float c3 = cp[(m + 3) * NF + f];
    const float4 b0 = bt.b[m * 4 + 0];
    const float4 b1 = bt.b[m * 4 + 1];
    const float4 b2 = bt.b[m * 4 + 2];
    const float4 b3 = bt.b[m * 4 + 3];
    float4 A;
    A.x = fmaf(c0, b0.x, fmaf(c1, b1.x, fmaf(c2, b2.x, fmaf(c3, b3.x, bias[f]))));
    A.y = fmaf(c0, b0.y, fmaf(c1, b1.y, fmaf(c2, b2.y, c3 * b3.y)));
    A.z = fmaf(c0, b0.z, fmaf(c1, b1.z, fmaf(c2, b2.z, c3 * b3.z)));
    A.w = fmaf(c0, b0.w, fmaf(c1, b1.w, fmaf(c2, b2.w, c3 * b3.w)));
    g_table[idx] = A;
}

// ---- consumer: copy quarter-table to smem, evaluate (pipelined) ----
template <bool GUARD>
__global__ void __launch_bounds__(TBE, 5)
bspline_eval_kernel(const float* __restrict__ x,
                    float* __restrict__ out,
                    int B)
{
    __shared__ float4 table[QT_ENTRIES];    // [61][32] this CTA's quarter

    const int tid  = threadIdx.x;
    const int q    = blockIdx.x & 3;        // feature quarter
    const int tile = blockIdx.x >> 2;       // row tile
    const int lane = tid & 31;              // local feature 0..31
    const int wrp  = tid >> 5;              // 0..7
    const int fg   = q * FQ + lane;         // global feature

    // ---- copy quarter of the table (coalesced LDG.128, L2-hot) ----
    {
        const float4* __restrict__ src = g_table + q * FQ;
#pragma unroll
        for (int it = 0; it < (QT_ENTRIES + TBE - 1) / TBE; it++) {
            const int idx = tid + it * TBE;
            if (idx < QT_ENTRIES) {
                const int m  = idx >> 5;
                const int ff = idx & 31;
                table[idx] = src[m * NF + ff];
            }
        }
    }
    __syncthreads();

    // ---- eval: warp owns 16 consecutive rows; 4 chunks of 4, double-buffered x ----
    const int rowBase = tile * RPB + wrp * 16;
    const float* __restrict__ xp = x + rowBase * NF + fg;
    float* __restrict__ op       = out + rowBase * NF + fg;

    float xv[UC];
#pragma unroll
    for (int j = 0; j < UC; j++) {
        if (!GUARD || rowBase + j < B) xv[j] = xp[j * NF];
    }

#pragma unroll
    for (int c = 0; c < NCH; c++) {
        // prefetch next chunk's x while this chunk computes
        float xn[UC];
        if (c < NCH - 1) {
#pragma unroll
            for (int j = 0; j < UC; j++) {
                const int row = rowBase + (c + 1) * UC + j;
                if (!GUARD || row < B) xn[j] = xp[((c + 1) * UC + j) * NF];
            }
        }

        float  t[UC];
        float4 A[UC];
#pragma unroll
        for (int j = 0; j < UC; j++) {
            const float u  = xv[j] * 61.0f;
            const float fm = floorf(u);      // x in [0,1) -> m in [0,60]
            t[j] = u - fm;
            A[j] = table[(int)fm * FQ + lane];   // conflict-free LDS.128
        }
#pragma unroll
        for (int j = 0; j < UC; j++) {
            float r = fmaf(A[j].w, t[j], A[j].z);
            r = fmaf(r, t[j], A[j].y);
            r = fmaf(r, t[j], A[j].x);
            const int row = rowBase + c * UC + j;
            if (!GUARD || row < B) op[(c * UC + j) * NF] = r;
        }

#pragma unroll
        for (int j = 0; j < UC; j++) xv[j] = xn[j];
    }
}

// ---- host-side basis polynomial construction (input-independent) ----
static inline double knotd(int im3) {
    double v = (double)im3;
    if (v < 0.0) v = 0.0;
    if (v > 61.0) v = 61.0;
    return v;
}

static void build_basis(BasisTab* bt)
{
    for (int m = 0; m < NSPAN; m++) {
        double P[4][4];
        memset(P, 0, sizeof(P));
        P[0][0] = 1.0;   // k=0: N_{m+3}^0 = 1 on the span

        for (int k = 1; k <= 3; k++) {
            double Q[4][4];
            memset(Q, 0, sizeof(Q));
            for (int j = 0; j <= k; j++) {
                const int i = m + 3 - k + j;
                const double ti   = knotd(i - 3);
                const double ti1  = knotd(i - 2);
                const double tik  = knotd(i - 3 + k);
                const double tik1 = knotd(i - 2 + k);
                if (j >= 1 && tik != ti) {
                    const double inv = 1.0 / (tik - ti);
                    const double a0  = ((double)m - ti) * inv;
                    for (int c = 0; c < 4; c++) Q[j][c]     += a0  * P[j - 1][c];
                    for (int c = 0; c < 3; c++) Q[j][c + 1] += inv * P[j - 1][c];
                }
                if (j <= k - 1 && tik1 != ti1) {
                    const double inv = 1.0 / (tik1 - ti1);
                    const double b0  = (tik1 - (double)m) * inv;
                    for (int c = 0; c < 4; c++) Q[j][c]     += b0  * P[j][c];
                    for (int c = 0; c < 3; c++) Q[j][c + 1] -= inv * P[j][c];
                }
            }
            memcpy(P, Q, sizeof(P));
        }
        for (int r = 0; r < 4; r++) {
            bt->b[m * 4 + r].x = (float)P[r][0];
            bt->b[m * 4 + r].y = (float)P[r][1];
            bt->b[m * 4 + r].z = (float)P[r][2];
            bt->b[m * 4 + r].w = (float)P[r][3];
        }
    }
}

extern "C" void kernel_launch(void* const* d_in, const int* in_sizes, int n_in,
                              void* d_out, int out_size)
{
    const float* x    = (const float*)d_in[0];
    const float* cp   = (const float*)d_in[1];
    const float* bias = (const float*)d_in[2];
    float* out = (float*)d_out;

    const int B = in_sizes[0] / NF;   // 16384 rows

    static BasisTab bt;
    build_basis(&bt);                 // deterministic per call

    // producer: build the 61x128 coefficient table once
    build_table_kernel<<<(TAB_ENTRIES + TBP - 1) / TBP, TBP>>>(bt, cp, bias);

    // consumer: evaluate (4 feature-quarters x row tiles)
    if ((B % RPB) == 0) {
        const int grid = (B / RPB) * 4;                 // 512 CTAs
        bspline_eval_kernel<false><<<grid, TBE>>>(x, out, B);
    } else {
        const int grid = ((B + RPB - 1) / RPB) * 4;
        bspline_eval_kernel<true><<<grid, TBE>>>(x, out, B);
    }
}